// round 4
// baseline (speedup 1.0000x reference)
#include <cuda_runtime.h>

#define NN 20000      // nodes
#define NE 100000     // edges
#define NF 64         // node feature dim (in)
#define EFD 32        // edge feature dim
#define FH 128        // heads * out_dim = 2*64
#define NH 2          // heads
#define DH 64         // out dim per head

// ---------------- scratch (device globals; no allocation allowed) ----------
__device__ __align__(16) float g_ft[NN * FH];   // node features after fc  [N, H*D]
__device__ __align__(16) float g_fe[NE * FH];   // edge features after fc  [E, H*D]
__device__ __align__(16) float g_el[NN * NH];
__device__ __align__(16) float g_er[NN * NH];
__device__ __align__(16) float g_h [NN * NF];   // inter-layer features
__device__ __align__(16) float g_h2[NN * NF];
__device__ float g_swr[NH * EFD];               // reduced edge-attn weights
// CSR (dst -> edges), built once per call
__device__ int g_deg[NN];
__device__ int g_off[NN + 1];
__device__ int g_cur[NN];
__device__ int g_eidx[NE];

// ================= CSR build ================================================
__global__ void zerodeg_kernel()
{
    const int i = blockIdx.x * blockDim.x + threadIdx.x;
    if (i < NN) g_deg[i] = 0;
}

__global__ void hist_kernel(const int* __restrict__ dst)
{
    const int e = blockIdx.x * blockDim.x + threadIdx.x;
    if (e < NE) atomicAdd(&g_deg[dst[e]], 1);
}

#define SCAN_T 1024
#define CHUNK 20           // 1024*20 >= 20000
__global__ __launch_bounds__(SCAN_T) void scan_kernel()
{
    __shared__ int sp[SCAN_T];
    const int t = threadIdx.x;
    const int base = t * CHUNK;
    int local[CHUNK];
    int sum = 0;
#pragma unroll
    for (int i = 0; i < CHUNK; i++) {
        const int idx = base + i;
        local[i] = sum;
        sum += (idx < NN) ? g_deg[idx] : 0;
    }
    sp[t] = sum;
    __syncthreads();
    for (int o = 1; o < SCAN_T; o <<= 1) {
        int v = 0;
        if (t >= o) v = sp[t - o];
        __syncthreads();
        if (t >= o) sp[t] += v;
        __syncthreads();
    }
    const int basesum = sp[t] - sum;   // exclusive base for this chunk
#pragma unroll
    for (int i = 0; i < CHUNK; i++) {
        const int idx = base + i;
        if (idx < NN) {
            const int o = basesum + local[i];
            g_off[idx] = o;
            g_cur[idx] = o;
        }
    }
    if (t == SCAN_T - 1) g_off[NN] = basesum + sum;
}

__global__ void scatter_kernel(const int* __restrict__ dst)
{
    const int e = blockIdx.x * blockDim.x + threadIdx.x;
    if (e >= NE) return;
    const int pos = atomicAdd(&g_cur[dst[e]], 1);
    g_eidx[pos] = e;
}

// ================= per-layer kernels ========================================

// reduced edge-attn weights: swr[h][k] = sum_d We[k, h*64+d] * ae[h*64+d]
__global__ void prep_kernel(const float* __restrict__ We, const float* __restrict__ ae)
{
    const int t = threadIdx.x;      // 64 threads
    const int h = t >> 5, k = t & 31;
    float v = 0.f;
#pragma unroll
    for (int d = 0; d < DH; d++) v = fmaf(We[k * FH + h * DH + d], ae[h * DH + d], v);
    g_swr[h * EFD + k] = v;
}

// node transform: ft = x @ Wn, el/er attention dots
__global__ __launch_bounds__(128) void node_kernel(
        const float* __restrict__ x, const float* __restrict__ Wn,
        const float* __restrict__ al, const float* __restrict__ ar)
{
    const int c = threadIdx.x;                 // output column 0..127
    const int n0 = blockIdx.x * 16;
    float w[NF];
#pragma unroll
    for (int k = 0; k < NF; k++) w[k] = Wn[k * FH + c];
    const float alc = al[c], arc = ar[c];

    __shared__ float sx[16][NF];
#pragma unroll
    for (int i = 0; i < 8; i++) {
        int idx = i * 128 + c;
        sx[idx >> 6][idx & 63] = x[n0 * NF + idx];
    }
    __syncthreads();

    __shared__ float swl[4], swr[4];
    const int wid = c >> 5, lane = c & 31;
    for (int i = 0; i < 16; i++) {
        const int n = n0 + i;
        float f = 0.f;
#pragma unroll
        for (int k = 0; k < NF; k++) f = fmaf(sx[i][k], w[k], f);
        g_ft[n * FH + c] = f;
        float vl = f * alc, vr = f * arc;
#pragma unroll
        for (int o = 16; o; o >>= 1) {
            vl += __shfl_down_sync(0xffffffffu, vl, o);
            vr += __shfl_down_sync(0xffffffffu, vr, o);
        }
        if (lane == 0) { swl[wid] = vl; swr[wid] = vr; }
        __syncthreads();
        if (c < NH) {
            g_el[n * NH + c] = swl[2 * c] + swl[2 * c + 1];
            g_er[n * NH + c] = swr[2 * c] + swr[2 * c + 1];
        }
        __syncthreads();
    }
}

// edge transform: fe = ef @ We
#define EPB 32
__global__ __launch_bounds__(128) void edge_kernel(
        const float* __restrict__ ef, const float* __restrict__ We)
{
    const int c = threadIdx.x;
    const int e0 = blockIdx.x * EPB;
    float w[EFD];
#pragma unroll
    for (int k = 0; k < EFD; k++) w[k] = We[k * FH + c];

    __shared__ float sx[EPB][EFD];
#pragma unroll
    for (int i = 0; i < EPB * EFD / 128; i++) {
        int idx = i * 128 + c;
        sx[idx >> 5][idx & 31] = ef[e0 * EFD + idx];
    }
    __syncthreads();

#pragma unroll 4
    for (int i = 0; i < EPB; i++) {
        float f = 0.f;
#pragma unroll
        for (int k = 0; k < EFD; k++) f = fmaf(sx[i][k], w[k], f);
        g_fe[(e0 + i) * FH + c] = f;
    }
}

// fused attention + softmax + message aggregation + bias + head-mean.
// warp per destination node; lane covers 4 feature columns (lanes 0-15 head0,
// 16-31 head1). out = (sum_e p_e * (ft[src]+fe[e])) / (sum_e p_e) + bias,
// then mean over heads.
__global__ __launch_bounds__(256) void agg_kernel(
        const float* __restrict__ ef, const int* __restrict__ src,
        const float* __restrict__ b, float* __restrict__ hout)
{
    __shared__ float sswr[NH * EFD];
    const int t = threadIdx.x;
    if (t < NH * EFD) sswr[t] = g_swr[t];
    __syncthreads();

    const int wid = t >> 5, lane = t & 31;
    const int n = blockIdx.x * 8 + wid;       // 2500 blocks * 8 warps = 20000
    const float w0 = sswr[lane], w1 = sswr[EFD + lane];
    const float2 er2 = *(const float2*)&g_er[n * NH];
    const int start = g_off[n], end = g_off[n + 1];

    float4 acc = make_float4(0.f, 0.f, 0.f, 0.f);
    float s0 = 0.f, s1 = 0.f;

    for (int j = start; j < end; j++) {
        const int eid = g_eidx[j];
        const int sn = src[eid];
        // ee[h] = dot(ef[eid], swr[h])  (warp-parallel over k)
        const float efv = ef[(size_t)eid * EFD + lane];
        float d0 = efv * w0, d1 = efv * w1;
#pragma unroll
        for (int o = 16; o; o >>= 1) {
            d0 += __shfl_xor_sync(0xffffffffu, d0, o);
            d1 += __shfl_xor_sync(0xffffffffu, d1, o);
        }
        const float2 el2 = *(const float2*)&g_el[sn * NH];
        float l0 = el2.x + er2.x + d0;
        float l1 = el2.y + er2.y + d1;
        l0 = (l0 > 0.f) ? l0 : 0.2f * l0;
        l1 = (l1 > 0.f) ? l1 : 0.2f * l1;
        const float p0 = __expf(l0), p1 = __expf(l1);
        s0 += p0; s1 += p1;
        const float ph = (lane < 16) ? p0 : p1;
        const float4 ft4 = __ldg((const float4*)&g_ft[(size_t)sn * FH + lane * 4]);
        const float4 fe4 = __ldg((const float4*)&g_fe[(size_t)eid * FH + lane * 4]);
        acc.x = fmaf(ft4.x + fe4.x, ph, acc.x);
        acc.y = fmaf(ft4.y + fe4.y, ph, acc.y);
        acc.z = fmaf(ft4.z + fe4.z, ph, acc.z);
        acc.w = fmaf(ft4.w + fe4.w, ph, acc.w);
    }

    const float sh = (lane < 16) ? s0 : s1;
    const float inv = (sh > 0.f) ? 1.f / sh : 0.f;    // deg-0 node -> msg = 0
    const float4 b4 = __ldg((const float4*)&b[lane * 4]);
    float4 tv;
    tv.x = fmaf(acc.x, inv, b4.x);
    tv.y = fmaf(acc.y, inv, b4.y);
    tv.z = fmaf(acc.z, inv, b4.z);
    tv.w = fmaf(acc.w, inv, b4.w);
    // head mean: pair lane L with L^16
    float4 pv;
    pv.x = __shfl_xor_sync(0xffffffffu, tv.x, 16);
    pv.y = __shfl_xor_sync(0xffffffffu, tv.y, 16);
    pv.z = __shfl_xor_sync(0xffffffffu, tv.z, 16);
    pv.w = __shfl_xor_sync(0xffffffffu, tv.w, 16);
    if (lane < 16) {
        float4 r;
        r.x = 0.5f * (tv.x + pv.x);
        r.y = 0.5f * (tv.y + pv.y);
        r.z = 0.5f * (tv.z + pv.z);
        r.w = 0.5f * (tv.w + pv.w);
        *(float4*)&hout[(size_t)n * DH + lane * 4] = r;
    }
}

// encoder-to-decoder: h @ W^T (W is [64,64] row-major)
__global__ __launch_bounds__(64) void e2d_kernel(
        const float* __restrict__ hin, const float* __restrict__ W,
        float* __restrict__ hout)
{
    const int j = threadIdx.x;                 // 0..63
    const int n0 = blockIdx.x * 16;
    float w[64];
#pragma unroll
    for (int k = 0; k < 64; k++) w[k] = W[j * 64 + k];
    __shared__ float sx[16][64];
    for (int i = j; i < 16 * 64; i += 64)
        sx[i >> 6][i & 63] = hin[n0 * 64 + i];
    __syncthreads();
    for (int i = 0; i < 16; i++) {
        float acc = 0.f;
#pragma unroll
        for (int k = 0; k < 64; k++) acc = fmaf(sx[i][k], w[k], acc);
        hout[(n0 + i) * 64 + j] = acc;
    }
}

// ---------------- host-side driver ------------------------------------------
static void run_layer(const float* xin, const float* ef,
                      const int* src,
                      const float* Wn, const float* We,
                      const float* al, const float* ar,
                      const float* ae, const float* b, float* hout)
{
    prep_kernel<<<1, 64>>>(We, ae);
    node_kernel<<<NN / 16, 128>>>(xin, Wn, al, ar);
    edge_kernel<<<NE / EPB, 128>>>(ef, We);
    agg_kernel<<<NN / 8, 256>>>(ef, src, b, hout);
}

extern "C" void kernel_launch(void* const* d_in, const int* in_sizes, int n_in,
                              void* d_out, int out_size)
{
    const float* x   = (const float*)d_in[0];
    const float* e   = (const float*)d_in[1];
    const int*   src = (const int*)  d_in[2];
    const int*   dst = (const int*)  d_in[3];

    // Only the LAST snapshot contributes to the output (decoded[-1]).
    const int S = in_sizes[0] / (NN * NF);
    const float* xs = x   + (size_t)(S - 1) * NN * NF;
    const float* es = e   + (size_t)(S - 1) * NE * EFD;
    const int*   ss = src + (size_t)(S - 1) * NE;
    const int*   ds = dst + (size_t)(S - 1) * NE;

    void *ph = nullptr, *ph2 = nullptr;
    cudaGetSymbolAddress(&ph,  g_h);
    cudaGetSymbolAddress(&ph2, g_h2);
    float* h  = (float*)ph;
    float* h2 = (float*)ph2;

    // Build CSR (dst -> edge list); graph identical for all 4 layers.
    zerodeg_kernel<<<(NN + 255) / 256, 256>>>();
    hist_kernel<<<(NE + 255) / 256, 256>>>(ds);
    scan_kernel<<<1, SCAN_T>>>();
    scatter_kernel<<<(NE + 255) / 256, 256>>>(ds);

    // Input order (setup_inputs dict insertion order):
    //   0:x 1:e 2:src 3:dst, 4..9:enc0, 10..15:enc1, 16..21:dec0, 22..27:dec1, 28:W_e2d
    run_layer(xs, es, ss,
              (const float*)d_in[4],  (const float*)d_in[5],
              (const float*)d_in[6],  (const float*)d_in[7],
              (const float*)d_in[8],  (const float*)d_in[9],  h);
    run_layer(h, es, ss,
              (const float*)d_in[10], (const float*)d_in[11],
              (const float*)d_in[12], (const float*)d_in[13],
              (const float*)d_in[14], (const float*)d_in[15], h2);
    e2d_kernel<<<NN / 16, 64>>>(h2, (const float*)d_in[28], h);
    run_layer(h, es, ss,
              (const float*)d_in[16], (const float*)d_in[17],
              (const float*)d_in[18], (const float*)d_in[19],
              (const float*)d_in[20], (const float*)d_in[21], h2);
    run_layer(h2, es, ss,
              (const float*)d_in[22], (const float*)d_in[23],
              (const float*)d_in[24], (const float*)d_in[25],
              (const float*)d_in[26], (const float*)d_in[27], (float*)d_out);
}

// round 5
// speedup vs baseline: 1.2021x; 1.2021x over previous
#include <cuda_runtime.h>

#define NN 20000      // nodes
#define NE 100000     // edges
#define NF 64         // node feature dim (in) — 64 for every layer here
#define EFD 32        // edge feature dim
#define FH 128        // heads * out_dim = 2*64
#define NH 2          // heads
#define DH 64         // out dim per head
#define EPB 32        // edges per block in edge kernel

// ---------------- scratch (device globals) ----------------------------------
__device__ __align__(16) float g_ft [NN * FH];    // node features after fc
__device__ __align__(16) float g_fes[NE * FH];    // fe in CSR-sorted order
__device__ __align__(16) float g_pls[NE * NH];    // el[src]+ee, CSR-sorted
__device__ int                 g_srcs[NE];        // src, CSR-sorted
__device__ __align__(16) float g_el[NN * NH];
__device__ __align__(16) float g_er[NN * NH];
__device__ __align__(16) float g_h [NN * NF];
__device__ __align__(16) float g_h2[NN * NF];
__device__ __align__(16) float g_Wp[NF * FH];     // W_e2d^T @ Wn_dec0
// reduced attention weights per layer
__device__ float g_redl[4][NH * NF];
__device__ float g_redr[4][NH * NF];
__device__ float g_rede[4][NH * EFD];
// CSR (dst -> edges)
__device__ int g_deg[NN];
__device__ int g_off[NN + 1];
__device__ int g_cur[NN];
__device__ int g_eidx[NE];

// ================= CSR build ================================================
__global__ void zerodeg_kernel()
{
    const int i = blockIdx.x * blockDim.x + threadIdx.x;
    if (i < NN) g_deg[i] = 0;
}

__global__ void hist_kernel(const int* __restrict__ dst)
{
    const int e = blockIdx.x * blockDim.x + threadIdx.x;
    if (e < NE) atomicAdd(&g_deg[dst[e]], 1);
}

#define SCAN_T 1024
#define CHUNK 20
__global__ __launch_bounds__(SCAN_T) void scan_kernel()
{
    __shared__ int sp[SCAN_T];
    const int t = threadIdx.x;
    const int base = t * CHUNK;
    int local[CHUNK];
    int sum = 0;
#pragma unroll
    for (int i = 0; i < CHUNK; i++) {
        const int idx = base + i;
        local[i] = sum;
        sum += (idx < NN) ? g_deg[idx] : 0;
    }
    sp[t] = sum;
    __syncthreads();
    for (int o = 1; o < SCAN_T; o <<= 1) {
        int v = 0;
        if (t >= o) v = sp[t - o];
        __syncthreads();
        if (t >= o) sp[t] += v;
        __syncthreads();
    }
    const int basesum = sp[t] - sum;
#pragma unroll
    for (int i = 0; i < CHUNK; i++) {
        const int idx = base + i;
        if (idx < NN) {
            const int o = basesum + local[i];
            g_off[idx] = o;
            g_cur[idx] = o;
        }
    }
    if (t == SCAN_T - 1) g_off[NN] = basesum + sum;
}

__global__ void scatter_kernel(const int* __restrict__ dst)
{
    const int e = blockIdx.x * blockDim.x + threadIdx.x;
    if (e >= NE) return;
    const int pos = atomicAdd(&g_cur[dst[e]], 1);
    g_eidx[pos] = e;
}

// ================= weight preprocessing =====================================
// Wp = W_e2d^T @ Wn_dec0  ([64,128]); fuses encoder_to_decoder into dec0 fc.
__global__ __launch_bounds__(256) void wfuse_kernel(
        const float* __restrict__ W_e2d, const float* __restrict__ Wn_dec0)
{
    const int i = blockIdx.x * blockDim.x + threadIdx.x;   // m*128 + c
    const int m = i >> 7, c = i & 127;
    float v = 0.f;
#pragma unroll
    for (int k = 0; k < NF; k++)
        v = fmaf(W_e2d[k * NF + m], Wn_dec0[k * FH + c], v);
    g_Wp[m * FH + c] = v;
}

struct PrepParams {
    const float *Wn[4], *We[4], *al[4], *ar[4], *ae[4];
};

// one block per layer; computes redl/redr [NH*NF] and rede [NH*EFD]
__global__ __launch_bounds__(256) void prep_kernel(PrepParams pp)
{
    const int lid = blockIdx.x;
    const int t = threadIdx.x;
    const float* Wn = pp.Wn[lid];
    const float* We = pp.We[lid];
    {   // redl / redr: 256 tasks = 2 types * 2 heads * 64 k
        const int type = t >> 7, r = t & 127;
        const int h = r >> 6, k = r & 63;
        const float* a = type ? pp.ar[lid] : pp.al[lid];
        float v = 0.f;
#pragma unroll
        for (int d = 0; d < DH; d++)
            v = fmaf(Wn[k * FH + h * DH + d], a[h * DH + d], v);
        (type ? g_redr : g_redl)[lid][h * NF + k] = v;
    }
    if (t < NH * EFD) {   // rede: 64 tasks
        const int h = t >> 5, k = t & 31;
        const float* ae = pp.ae[lid];
        float v = 0.f;
#pragma unroll
        for (int d = 0; d < DH; d++)
            v = fmaf(We[k * FH + h * DH + d], ae[h * DH + d], v);
        g_rede[lid][h * EFD + k] = v;
    }
}

// ================= per-layer kernels ========================================

// node transform: ft = x @ Wn; el/er via reduced weights (no shuffles, 1 sync)
__global__ __launch_bounds__(128) void node_kernel(
        const float* __restrict__ x, const float* __restrict__ Wn, int lid)
{
    const int c = threadIdx.x;
    const int n0 = blockIdx.x * 16;
    float w[NF];
#pragma unroll
    for (int k = 0; k < NF; k++) w[k] = Wn[k * FH + c];

    __shared__ float sx[16][NF + 1];
#pragma unroll
    for (int i = 0; i < 8; i++) {
        int idx = i * 128 + c;
        sx[idx >> 6][idx & 63] = x[n0 * NF + idx];
    }
    __syncthreads();

#pragma unroll 4
    for (int i = 0; i < 16; i++) {
        float f = 0.f;
#pragma unroll
        for (int k = 0; k < NF; k++) f = fmaf(sx[i][k], w[k], f);
        g_ft[(n0 + i) * FH + c] = f;
    }

    if (c < 64) {   // 64 tasks: type(2) x head(2) x node(16)
        const int type = c >> 5, h = (c >> 4) & 1, i = c & 15;
        const float* rd = (type ? g_redr : g_redl)[lid] + h * NF;
        float v = 0.f;
#pragma unroll
        for (int k = 0; k < NF; k++) v = fmaf(sx[i][k], rd[k], v);
        (type ? g_er : g_el)[(n0 + i) * NH + h] = v;
    }
}

// edge transform in CSR order: fe_s[j] = ef[eidx[j]] @ We,
// pl_s[j,h] = el[src,h] + dot(ef[eidx[j]], rede[h]), src_s[j] = src[eidx[j]]
__global__ __launch_bounds__(128) void edge_kernel(
        const float* __restrict__ ef, const float* __restrict__ We,
        const int* __restrict__ src, int lid)
{
    const int c = threadIdx.x;
    const int j0 = blockIdx.x * EPB;
    float w[EFD];
#pragma unroll
    for (int k = 0; k < EFD; k++) w[k] = We[k * FH + c];

    __shared__ int ssrc[EPB];
    __shared__ float sx[EPB][EFD + 1];
    __shared__ int seid[EPB];
    if (c < EPB) {
        const int e = g_eidx[j0 + c];
        seid[c] = e;
        const int sn = src[e];
        ssrc[c] = sn;
        g_srcs[j0 + c] = sn;
    }
    __syncthreads();
#pragma unroll
    for (int rep = 0; rep < EPB * EFD / 128; rep++) {
        const int idx = rep * 128 + c;
        const int row = idx >> 5, col = idx & 31;
        sx[row][col] = ef[(size_t)seid[row] * EFD + col];
    }
    __syncthreads();

    if (c < NH * EPB) {   // pl for 32 edges x 2 heads
        const int h = c >> 5, i = c & 31;
        const float* rd = g_rede[lid] + h * EFD;
        float v = 0.f;
#pragma unroll
        for (int k = 0; k < EFD; k++) v = fmaf(sx[i][k], rd[k], v);
        g_pls[(j0 + i) * NH + h] = v + g_el[ssrc[i] * NH + h];
    }

#pragma unroll 4
    for (int i = 0; i < EPB; i++) {
        float f = 0.f;
#pragma unroll
        for (int k = 0; k < EFD; k++) f = fmaf(sx[i][k], w[k], f);
        g_fes[(j0 + i) * FH + c] = f;
    }
}

// fused softmax + aggregation + bias + head-mean. warp per dst node.
__global__ __launch_bounds__(256) void agg_kernel(
        const float* __restrict__ b, float* __restrict__ hout)
{
    const int t = threadIdx.x;
    const int wid = t >> 5, lane = t & 31;
    const int n = blockIdx.x * 8 + wid;
    const float2 er2 = *(const float2*)&g_er[n * NH];
    const int start = g_off[n], end = g_off[n + 1];

    float4 acc = make_float4(0.f, 0.f, 0.f, 0.f);
    float s0 = 0.f, s1 = 0.f;

    for (int j = start; j < end; j++) {
        const int sn = g_srcs[j];                     // warp-broadcast
        const float2 pl = *(const float2*)&g_pls[j * NH];
        float l0 = pl.x + er2.x;
        float l1 = pl.y + er2.y;
        l0 = (l0 > 0.f) ? l0 : 0.2f * l0;
        l1 = (l1 > 0.f) ? l1 : 0.2f * l1;
        const float p0 = __expf(l0), p1 = __expf(l1);
        s0 += p0; s1 += p1;
        const float ph = (lane < 16) ? p0 : p1;
        const float4 ft4 = __ldg((const float4*)&g_ft[(size_t)sn * FH + lane * 4]);
        const float4 fe4 = __ldg((const float4*)&g_fes[(size_t)j * FH + lane * 4]);
        acc.x = fmaf(ft4.x + fe4.x, ph, acc.x);
        acc.y = fmaf(ft4.y + fe4.y, ph, acc.y);
        acc.z = fmaf(ft4.z + fe4.z, ph, acc.z);
        acc.w = fmaf(ft4.w + fe4.w, ph, acc.w);
    }

    const float sh = (lane < 16) ? s0 : s1;
    const float inv = (sh > 0.f) ? 1.f / sh : 0.f;   // deg-0 node -> msg = 0
    const float4 b4 = __ldg((const float4*)&b[lane * 4]);
    float4 tv;
    tv.x = fmaf(acc.x, inv, b4.x);
    tv.y = fmaf(acc.y, inv, b4.y);
    tv.z = fmaf(acc.z, inv, b4.z);
    tv.w = fmaf(acc.w, inv, b4.w);
    float4 pv;
    pv.x = __shfl_xor_sync(0xffffffffu, tv.x, 16);
    pv.y = __shfl_xor_sync(0xffffffffu, tv.y, 16);
    pv.z = __shfl_xor_sync(0xffffffffu, tv.z, 16);
    pv.w = __shfl_xor_sync(0xffffffffu, tv.w, 16);
    if (lane < 16) {
        float4 r;
        r.x = 0.5f * (tv.x + pv.x);
        r.y = 0.5f * (tv.y + pv.y);
        r.z = 0.5f * (tv.z + pv.z);
        r.w = 0.5f * (tv.w + pv.w);
        *(float4*)&hout[(size_t)n * DH + lane * 4] = r;
    }
}

// ---------------- host-side driver ------------------------------------------
static void run_layer(const float* xin, const float* ef, const int* src,
                      const float* Wn, const float* We,
                      const float* b, int lid, float* hout)
{
    node_kernel<<<NN / 16, 128>>>(xin, Wn, lid);
    edge_kernel<<<NE / EPB, 128>>>(ef, We, src, lid);
    agg_kernel<<<NN / 8, 256>>>(b, hout);
}

extern "C" void kernel_launch(void* const* d_in, const int* in_sizes, int n_in,
                              void* d_out, int out_size)
{
    const float* x   = (const float*)d_in[0];
    const float* e   = (const float*)d_in[1];
    const int*   src = (const int*)  d_in[2];
    const int*   dst = (const int*)  d_in[3];

    // Only the LAST snapshot contributes to the output (decoded[-1]).
    const int S = in_sizes[0] / (NN * NF);
    const float* xs = x   + (size_t)(S - 1) * NN * NF;
    const float* es = e   + (size_t)(S - 1) * NE * EFD;
    const int*   ss = src + (size_t)(S - 1) * NE;
    const int*   ds = dst + (size_t)(S - 1) * NE;

    void *ph = nullptr, *ph2 = nullptr, *pwp = nullptr;
    cudaGetSymbolAddress(&ph,  g_h);
    cudaGetSymbolAddress(&ph2, g_h2);
    cudaGetSymbolAddress(&pwp, g_Wp);
    float* h  = (float*)ph;
    float* h2 = (float*)ph2;
    const float* Wp = (const float*)pwp;

    // Input order (setup_inputs dict insertion order):
    //   0:x 1:e 2:src 3:dst, 4..9:enc0{Wn,We,al,ar,ae,b}, 10..15:enc1,
    //   16..21:dec0, 22..27:dec1, 28:W_e2d
    const float* P[29];
    for (int i = 4; i <= 28; i++) P[i] = (const float*)d_in[i];

    // CSR build (graph identical across all layers)
    zerodeg_kernel<<<(NN + 255) / 256, 256>>>();
    hist_kernel<<<(NE + 255) / 256, 256>>>(ds);
    scan_kernel<<<1, SCAN_T>>>();
    scatter_kernel<<<(NE + 255) / 256, 256>>>(ds);

    // fuse W_e2d into dec0 node weight, then reduced attn weights for all layers
    wfuse_kernel<<<NF * FH / 256, 256>>>(P[28], P[16]);
    PrepParams pp;
    // layer 0: enc0, 1: enc1, 2: dec0 (Wn := Wp), 3: dec1
    pp.Wn[0] = P[4];  pp.We[0] = P[5];  pp.al[0] = P[6];  pp.ar[0] = P[7];  pp.ae[0] = P[8];
    pp.Wn[1] = P[10]; pp.We[1] = P[11]; pp.al[1] = P[12]; pp.ar[1] = P[13]; pp.ae[1] = P[14];
    pp.Wn[2] = Wp;    pp.We[2] = P[17]; pp.al[2] = P[18]; pp.ar[2] = P[19]; pp.ae[2] = P[20];
    pp.Wn[3] = P[22]; pp.We[3] = P[23]; pp.al[3] = P[24]; pp.ar[3] = P[25]; pp.ae[3] = P[26];
    prep_kernel<<<4, 256>>>(pp);

    run_layer(xs, es, ss, P[4],  P[5],  P[9],  0, h);    // enc0
    run_layer(h,  es, ss, P[10], P[11], P[15], 1, h2);   // enc1
    run_layer(h2, es, ss, Wp,    P[17], P[21], 2, h);    // dec0 (e2d fused)
    run_layer(h,  es, ss, P[22], P[23], P[27], 3, (float*)d_out);  // dec1
}

// round 6
// speedup vs baseline: 1.3424x; 1.1168x over previous
#include <cuda_runtime.h>

#define NN 20000      // nodes
#define NE 100000     // edges
#define NF 64         // node feature dim (in) — 64 for every layer here
#define EFD 32        // edge feature dim
#define FH 128        // heads * out_dim = 2*64
#define NH 2          // heads
#define DH 64         // out dim per head

// ---------------- scratch (device globals) ----------------------------------
__device__ __align__(16) float g_el[NN * NH];
__device__ __align__(16) float g_er[NN * NH];
__device__ __align__(16) float g_xs[NN * FH];     // per-node weighted x sums (2 heads)
__device__ __align__(16) float g_us[NN * 2 * EFD];// per-node weighted ef sums (2 heads)
__device__ __align__(16) float g_ss[NN * NH];     // softmax denominators
__device__ __align__(16) float g_h [NN * NF];
__device__ __align__(16) float g_h2[NN * NF];
__device__ __align__(16) float g_Wp[NF * FH];     // W_e2d^T @ Wn_dec0
__device__ __align__(16) float g_efs[NE * EFD];   // ef rows in CSR order
__device__ __align__(8)  float g_eeall[4][NE * NH]; // ee per layer, CSR order
__device__ int g_srcs[NE];                        // src in CSR order
// reduced attention weights per layer
__device__ float g_redl[4][NH * NF];
__device__ float g_redr[4][NH * NF];
__device__ float g_rede[4][NH * EFD];
// CSR (dst -> edges)
__device__ int g_deg[NN];
__device__ int g_off[NN + 1];
__device__ int g_cur[NN];
__device__ int g_eidx[NE];

// ================= CSR build ================================================
__global__ void zerodeg_kernel()
{
    const int i = blockIdx.x * blockDim.x + threadIdx.x;
    if (i < NN) g_deg[i] = 0;
}

__global__ void hist_kernel(const int* __restrict__ dst)
{
    const int e = blockIdx.x * blockDim.x + threadIdx.x;
    if (e < NE) atomicAdd(&g_deg[dst[e]], 1);
}

#define SCAN_T 1024
#define CHUNK 20
__global__ __launch_bounds__(SCAN_T) void scan_kernel()
{
    __shared__ int sp[SCAN_T];
    const int t = threadIdx.x;
    const int base = t * CHUNK;
    int local[CHUNK];
    int sum = 0;
#pragma unroll
    for (int i = 0; i < CHUNK; i++) {
        const int idx = base + i;
        local[i] = sum;
        sum += (idx < NN) ? g_deg[idx] : 0;
    }
    sp[t] = sum;
    __syncthreads();
    for (int o = 1; o < SCAN_T; o <<= 1) {
        int v = 0;
        if (t >= o) v = sp[t - o];
        __syncthreads();
        if (t >= o) sp[t] += v;
        __syncthreads();
    }
    const int basesum = sp[t] - sum;
#pragma unroll
    for (int i = 0; i < CHUNK; i++) {
        const int idx = base + i;
        if (idx < NN) {
            const int o = basesum + local[i];
            g_off[idx] = o;
            g_cur[idx] = o;
        }
    }
    if (t == SCAN_T - 1) g_off[NN] = basesum + sum;
}

__global__ void scatter_kernel(const int* __restrict__ dst)
{
    const int e = blockIdx.x * blockDim.x + threadIdx.x;
    if (e >= NE) return;
    const int pos = atomicAdd(&g_cur[dst[e]], 1);
    g_eidx[pos] = e;
}

// gather src + ef rows into CSR order (once; shared by all 4 layers)
__global__ __launch_bounds__(128) void gather_kernel(
        const float* __restrict__ ef, const int* __restrict__ src)
{
    const int c = threadIdx.x;
    const int j0 = blockIdx.x * 32;
    __shared__ int seid[32];
    if (c < 32) {
        const int e = g_eidx[j0 + c];
        seid[c] = e;
        g_srcs[j0 + c] = src[e];
    }
    __syncthreads();
#pragma unroll
    for (int rep = 0; rep < 2; rep++) {          // 32 edges * 8 float4 = 256
        const int idx = rep * 128 + c;
        const int row = idx >> 3, col = idx & 7;
        const float4 v = __ldg((const float4*)&ef[(size_t)seid[row] * EFD + col * 4]);
        *(float4*)&g_efs[(size_t)(j0 + row) * EFD + col * 4] = v;
    }
}

// ================= weight preprocessing =====================================
// Wp = W_e2d^T @ Wn_dec0  ([64,128]); fuses encoder_to_decoder into dec0 fc.
__global__ __launch_bounds__(256) void wfuse_kernel(
        const float* __restrict__ W_e2d, const float* __restrict__ Wn_dec0)
{
    const int i = blockIdx.x * blockDim.x + threadIdx.x;   // m*128 + c
    const int m = i >> 7, c = i & 127;
    float v = 0.f;
#pragma unroll
    for (int k = 0; k < NF; k++)
        v = fmaf(W_e2d[k * NF + m], Wn_dec0[k * FH + c], v);
    g_Wp[m * FH + c] = v;
}

struct PrepParams {
    const float *Wn[4], *We[4], *al[4], *ar[4], *ae[4];
};

// one block per layer; computes redl/redr [NH*NF] and rede [NH*EFD]
__global__ __launch_bounds__(256) void prep_kernel(PrepParams pp)
{
    const int lid = blockIdx.x;
    const int t = threadIdx.x;
    const float* Wn = pp.Wn[lid];
    const float* We = pp.We[lid];
    {   // redl / redr: 256 tasks = 2 types * 2 heads * 64 k
        const int type = t >> 7, r = t & 127;
        const int h = r >> 6, k = r & 63;
        const float* a = type ? pp.ar[lid] : pp.al[lid];
        float v = 0.f;
#pragma unroll
        for (int d = 0; d < DH; d++)
            v = fmaf(Wn[k * FH + h * DH + d], a[h * DH + d], v);
        (type ? g_redr : g_redl)[lid][h * NF + k] = v;
    }
    if (t < NH * EFD) {   // rede: 64 tasks
        const int h = t >> 5, k = t & 31;
        const float* ae = pp.ae[lid];
        float v = 0.f;
#pragma unroll
        for (int d = 0; d < DH; d++)
            v = fmaf(We[k * FH + h * DH + d], ae[h * DH + d], v);
        g_rede[lid][h * EFD + k] = v;
    }
}

// ee for all 4 layers in one pass over CSR-ordered ef
__global__ __launch_bounds__(128) void eeall_kernel()
{
    const int c = threadIdx.x;
    const int j0 = blockIdx.x * 32;
    __shared__ float sx[32][EFD + 1];
    for (int i = c; i < 32 * EFD; i += 128)
        sx[i >> 5][i & 31] = g_efs[(size_t)j0 * EFD + i];
    __syncthreads();
    const int lid = c >> 5, i = c & 31;
    const float* rd = g_rede[lid];
    float v0 = 0.f, v1 = 0.f;
#pragma unroll
    for (int k = 0; k < EFD; k++) {
        v0 = fmaf(sx[i][k], rd[k], v0);
        v1 = fmaf(sx[i][k], rd[EFD + k], v1);
    }
    *(float2*)&g_eeall[lid][(size_t)(j0 + i) * NH] = make_float2(v0, v1);
}

// ================= per-layer kernels ========================================

// el/er from x via reduced weights (node GEMM eliminated)
__global__ __launch_bounds__(128) void nodeattn_kernel(
        const float* __restrict__ x, int lid)
{
    const int c = threadIdx.x;
    const int n0 = blockIdx.x * 32;
    __shared__ float sx[32][NF + 1];
    for (int i = c; i < 32 * NF; i += 128)
        sx[i >> 6][i & 63] = x[(size_t)n0 * NF + i];
    __syncthreads();
    const int type = c >> 6, h = (c >> 5) & 1, i = c & 31;
    const float* rd = (type ? g_redr : g_redl)[lid] + h * NF;
    float v = 0.f;
#pragma unroll
    for (int k = 0; k < NF; k++) v = fmaf(sx[i][k], rd[k], v);
    (type ? g_er : g_el)[(n0 + i) * NH + h] = v;
}

// fused softmax + weighted-input aggregation. warp per dst node.
// accumulates xs_h = sum_e p_h * x[src], u_h = sum_e p_h * ef_e, s_h = sum_e p_h
__global__ __launch_bounds__(256) void agg_kernel(
        const float* __restrict__ x, int lid)
{
    const int t = threadIdx.x;
    const int wid = t >> 5, lane = t & 31;
    const int n = blockIdx.x * 8 + wid;
    const float2 er2 = *(const float2*)&g_er[n * NH];
    const int start = g_off[n], end = g_off[n + 1];
    const int xoff = (lane & 15) * 4;
    const float* eep = g_eeall[lid];

    float4 xa = make_float4(0.f, 0.f, 0.f, 0.f);
    float u0 = 0.f, u1 = 0.f, s0 = 0.f, s1 = 0.f;

    for (int j = start; j < end; j++) {
        const int sn = g_srcs[j];
        const float2 ee = *(const float2*)&eep[(size_t)j * NH];
        const float2 el2 = *(const float2*)&g_el[sn * NH];
        float l0 = el2.x + er2.x + ee.x;
        float l1 = el2.y + er2.y + ee.y;
        l0 = (l0 > 0.f) ? l0 : 0.2f * l0;
        l1 = (l1 > 0.f) ? l1 : 0.2f * l1;
        const float p0 = __expf(l0), p1 = __expf(l1);
        s0 += p0; s1 += p1;
        const float ph = (lane < 16) ? p0 : p1;
        const float4 x4 = __ldg((const float4*)&x[(size_t)sn * NF + xoff]);
        const float efv = g_efs[(size_t)j * EFD + lane];
        xa.x = fmaf(x4.x, ph, xa.x);
        xa.y = fmaf(x4.y, ph, xa.y);
        xa.z = fmaf(x4.z, ph, xa.z);
        xa.w = fmaf(x4.w, ph, xa.w);
        u0 = fmaf(efv, p0, u0);
        u1 = fmaf(efv, p1, u1);
    }

    *(float4*)&g_xs[(size_t)n * FH + lane * 4] = xa;   // [0:64)=h0, [64:128)=h1
    g_us[n * 2 * EFD + lane] = u0;                     // [0:32)=h0
    g_us[n * 2 * EFD + EFD + lane] = u1;               // [32:64)=h1
    if (lane == 0) {
        g_ss[n * NH + 0] = s0;
        g_ss[n * NH + 1] = s1;
    }
}

// finalize: out = ((xs_h @ Wn_h) + (u_h @ We_h))/s_h + b, mean over heads
__global__ __launch_bounds__(128) void fin_kernel(
        const float* __restrict__ Wn, const float* __restrict__ We,
        const float* __restrict__ b, float* __restrict__ hout)
{
    const int c = threadIdx.x;                 // c = h*64 + d
    const int n0 = blockIdx.x * 16;
    const int h = c >> 6;
    float wn[NF];
#pragma unroll
    for (int k = 0; k < NF; k++) wn[k] = Wn[k * FH + c];
    float we[EFD];
#pragma unroll
    for (int k = 0; k < EFD; k++) we[k] = We[k * FH + c];
    const float bc = b[c];

    __shared__ float sxs[16][FH];
    __shared__ float sus[16][2 * EFD];
    __shared__ float sss[16][NH];
    __shared__ float st [16][FH];
    for (int i = c; i < 16 * FH; i += 128) sxs[i >> 7][i & 127] = g_xs[(size_t)n0 * FH + i];
    for (int i = c; i < 16 * 2 * EFD; i += 128) sus[i >> 6][i & 63] = g_us[n0 * 2 * EFD + i];
    if (c < 16 * NH) sss[c >> 1][c & 1] = g_ss[n0 * NH + c];
    __syncthreads();

#pragma unroll 2
    for (int i = 0; i < 16; i++) {
        float a = 0.f;
#pragma unroll
        for (int k = 0; k < NF; k++) a = fmaf(sxs[i][h * NF + k], wn[k], a);
        float uu = 0.f;
#pragma unroll
        for (int k = 0; k < EFD; k++) uu = fmaf(sus[i][h * EFD + k], we[k], uu);
        const float s = sss[i][h];
        const float inv = (s > 0.f) ? 1.f / s : 0.f;   // deg-0 node -> msg = 0
        st[i][c] = fmaf(a + uu, inv, bc);
    }
    __syncthreads();

    for (int i = c; i < 16 * DH; i += 128) {
        const int ni = i >> 6, d = i & 63;
        hout[(size_t)(n0 + ni) * DH + d] = 0.5f * (st[ni][d] + st[ni][DH + d]);
    }
}

// ---------------- host-side driver ------------------------------------------
static void run_layer(const float* xin, const float* Wn, const float* We,
                      const float* b, int lid, float* hout)
{
    nodeattn_kernel<<<NN / 32, 128>>>(xin, lid);
    agg_kernel<<<NN / 8, 256>>>(xin, lid);
    fin_kernel<<<NN / 16, 128>>>(Wn, We, b, hout);
}

extern "C" void kernel_launch(void* const* d_in, const int* in_sizes, int n_in,
                              void* d_out, int out_size)
{
    const float* x   = (const float*)d_in[0];
    const float* e   = (const float*)d_in[1];
    const int*   src = (const int*)  d_in[2];
    const int*   dst = (const int*)  d_in[3];

    // Only the LAST snapshot contributes to the output (decoded[-1]).
    const int S = in_sizes[0] / (NN * NF);
    const float* xs = x   + (size_t)(S - 1) * NN * NF;
    const float* es = e   + (size_t)(S - 1) * NE * EFD;
    const int*   ss = src + (size_t)(S - 1) * NE;
    const int*   ds = dst + (size_t)(S - 1) * NE;

    void *ph = nullptr, *ph2 = nullptr, *pwp = nullptr;
    cudaGetSymbolAddress(&ph,  g_h);
    cudaGetSymbolAddress(&ph2, g_h2);
    cudaGetSymbolAddress(&pwp, g_Wp);
    float* h  = (float*)ph;
    float* h2 = (float*)ph2;
    const float* Wp = (const float*)pwp;

    // Input order (setup_inputs dict insertion order):
    //   0:x 1:e 2:src 3:dst, 4..9:enc0{Wn,We,al,ar,ae,b}, 10..15:enc1,
    //   16..21:dec0, 22..27:dec1, 28:W_e2d
    const float* P[29];
    for (int i = 4; i <= 28; i++) P[i] = (const float*)d_in[i];

    // CSR build + one-time gathers (graph identical across all layers)
    zerodeg_kernel<<<(NN + 255) / 256, 256>>>();
    hist_kernel<<<(NE + 255) / 256, 256>>>(ds);
    scan_kernel<<<1, SCAN_T>>>();
    scatter_kernel<<<(NE + 255) / 256, 256>>>(ds);
    gather_kernel<<<NE / 32, 128>>>(es, ss);

    // weight preprocessing
    wfuse_kernel<<<NF * FH / 256, 256>>>(P[28], P[16]);
    PrepParams pp;
    pp.Wn[0] = P[4];  pp.We[0] = P[5];  pp.al[0] = P[6];  pp.ar[0] = P[7];  pp.ae[0] = P[8];
    pp.Wn[1] = P[10]; pp.We[1] = P[11]; pp.al[1] = P[12]; pp.ar[1] = P[13]; pp.ae[1] = P[14];
    pp.Wn[2] = Wp;    pp.We[2] = P[17]; pp.al[2] = P[18]; pp.ar[2] = P[19]; pp.ae[2] = P[20];
    pp.Wn[3] = P[22]; pp.We[3] = P[23]; pp.al[3] = P[24]; pp.ar[3] = P[25]; pp.ae[3] = P[26];
    prep_kernel<<<4, 256>>>(pp);
    eeall_kernel<<<NE / 32, 128>>>();

    run_layer(xs, P[4],  P[5],  P[9],  0, h);               // enc0
    run_layer(h,  P[10], P[11], P[15], 1, h2);              // enc1
    run_layer(h2, Wp,    P[17], P[21], 2, h);               // dec0 (e2d fused)
    run_layer(h,  P[22], P[23], P[27], 3, (float*)d_out);   // dec1
}